// round 3
// baseline (speedup 1.0000x reference)
#include <cuda_runtime.h>
#include <math_constants.h>

#define NQ    4096
#define NKV   32768
#define CDIM  256
#define KNN   100
#define CAP   4096
#define TILE  2048
#define QPW   4          // queries per warp (scan kernel)
#define WPB   4          // warps per block (scan kernel)
#define SMAX  2048       // smem slice capacity in final kernel
#define FULLM 0xffffffffu

// ---------------- static scratch ----------------
__device__ float g_bufd[(size_t)NQ * CAP];
__device__ int   g_bufi[(size_t)NQ * CAP];
__device__ int   g_cnt[NQ];
__device__ int   g_topk[(size_t)NQ * KNN];

// ---------------- helpers ----------------
__device__ __forceinline__ int warp_sum_i(int v) {
#pragma unroll
    for (int o = 16; o; o >>= 1) v += __shfl_xor_sync(FULLM, v, o);
    return v;
}
__device__ __forceinline__ float warp_sum_f(float v) {
#pragma unroll
    for (int o = 16; o; o >>= 1) v += __shfl_xor_sync(FULLM, v, o);
    return v;
}
__device__ __forceinline__ float warp_max_f(float v) {
#pragma unroll
    for (int o = 16; o; o >>= 1) v = fmaxf(v, __shfl_xor_sync(FULLM, v, o));
    return v;
}
__device__ __forceinline__ int warp_min_i(int v) {
#pragma unroll
    for (int o = 16; o; o >>= 1) v = min(v, __shfl_xor_sync(FULLM, v, o));
    return v;
}

// ================= kernel 1: candidate scan =================
// Per warp: 4 queries. Sample phase (first TILE candidates) builds a per-lane
// sorted-4 minimum stash -> safe threshold (>= true 100th dist). Main scan
// appends all candidates with d <= thr to a per-query global buffer.
__global__ void __launch_bounds__(32 * WPB) knn_scan(
    const float* __restrict__ qpos, const float* __restrict__ kpos)
{
    __shared__ float4 s_tile[TILE];
    __shared__ int    s_cnt[WPB * QPW];

    const int tid = threadIdx.x, lane = tid & 31, warp = tid >> 5;
    const int qbase = blockIdx.x * (WPB * QPW) + warp * QPW;

    float ax[QPW], ay[QPW], az[QPW], c0[QPW], thr[QPW];
#pragma unroll
    for (int j = 0; j < QPW; j++) {
        int q = qbase + j;
        float qx = qpos[3 * q], qy = qpos[3 * q + 1], qz = qpos[3 * q + 2];
        c0[j] = fmaf(qx, qx, fmaf(qy, qy, qz * qz));
        ax[j] = -2.f * qx; ay[j] = -2.f * qy; az[j] = -2.f * qz;
    }

    // tile 0 load (also used by sample phase)
    for (int i = tid; i < TILE; i += 32 * WPB) {
        float x = kpos[3 * i], y = kpos[3 * i + 1], z = kpos[3 * i + 2];
        s_tile[i] = make_float4(x, y, z, fmaf(x, x, fmaf(y, y, z * z)));
    }
    if (tid < WPB * QPW) s_cnt[tid] = 0;
    __syncthreads();

    // ---- sample: per-lane sorted-4 minima per query ----
    float m[QPW][4];
#pragma unroll
    for (int j = 0; j < QPW; j++)
#pragma unroll
        for (int s = 0; s < 4; s++) m[j][s] = CUDART_INF_F;

    for (int i = lane; i < TILE; i += 32) {
        float4 kp = s_tile[i];
#pragma unroll
        for (int j = 0; j < QPW; j++) {
            float d = fmaf(ax[j], kp.x, c0[j] + kp.w);
            d = fmaf(ay[j], kp.y, d);
            d = fmaf(az[j], kp.z, d);
            d = fmaxf(d, 0.f);
            // branchless sorted insert into m[j][0..3] (ascending)
            float t0 = fminf(m[j][0], d), t1 = fmaxf(m[j][0], d); m[j][0] = t0;
            float t2 = fminf(m[j][1], t1), t3 = fmaxf(m[j][1], t1); m[j][1] = t2;
            float t4 = fminf(m[j][2], t3), t5 = fmaxf(m[j][2], t3); m[j][2] = t4;
            m[j][3] = fminf(m[j][3], t5);
        }
    }

    // thr[j] = upper bound on 100th smallest of the 128 stash values
    // (subset of sample => >= sample 100th >= global 100th : safe filter)
#pragma unroll
    for (int j = 0; j < QPW; j++) {
        unsigned lo = 0u, hi = 0x7f800000u;
#pragma unroll
        for (int it = 0; it < 16; it++) {
            unsigned mid = lo + ((hi - lo) >> 1);
            int c = 0;
#pragma unroll
            for (int s = 0; s < 4; s++) c += (__float_as_uint(m[j][s]) <= mid) ? 1 : 0;
            c = warp_sum_i(c);
            if (c >= KNN) hi = mid; else lo = mid + 1u;
        }
        thr[j] = __uint_as_float(hi);
    }

    // ---- main scan ----
    for (int t0 = 0; t0 < NKV; t0 += TILE) {
        if (t0) {
            __syncthreads();
            for (int i = tid; i < TILE; i += 32 * WPB) {
                int g = t0 + i;
                float x = kpos[3 * g], y = kpos[3 * g + 1], z = kpos[3 * g + 2];
                s_tile[i] = make_float4(x, y, z, fmaf(x, x, fmaf(y, y, z * z)));
            }
            __syncthreads();
        }
        for (int i = lane; i < TILE; i += 32) {
            float4 kp = s_tile[i];
            float d[QPW]; bool p[QPW]; bool anyp = false;
#pragma unroll
            for (int j = 0; j < QPW; j++) {
                float dd = fmaf(ax[j], kp.x, c0[j] + kp.w);
                dd = fmaf(ay[j], kp.y, dd);
                dd = fmaf(az[j], kp.z, dd);
                d[j] = dd;
                p[j] = (dd <= thr[j]);
                anyp |= p[j];
            }
            if (__any_sync(FULLM, anyp)) {
#pragma unroll
                for (int j = 0; j < QPW; j++) {
                    if (p[j]) {
                        int pos = atomicAdd(&s_cnt[warp * QPW + j], 1);
                        if (pos < CAP) {
                            size_t b = (size_t)(qbase + j) * CAP + pos;
                            g_bufd[b] = fmaxf(d[j], 0.f);
                            g_bufi[b] = t0 + i;
                        }
                    }
                }
            }
        }
    }
    __syncthreads();
    if (tid < WPB * QPW)
        g_cnt[blockIdx.x * (WPB * QPW) + tid] = min(s_cnt[tid], CAP);
}

// ================= kernel 2: exact top-100 from candidates =================
// Warp per query. Candidates copied to smem (global fallback if >SMAX).
// Exact 100th value via binary search on float bits; ties resolved to the
// smallest indices (matches jax stable top_k set).
__global__ void __launch_bounds__(64) knn_final()
{
    __shared__ float sd[2][SMAX];
    __shared__ int   si[2][SMAX];
    __shared__ int   s_tie[2][32];

    const int lane = threadIdx.x & 31, w = threadIdx.x >> 5;
    const int q = blockIdx.x * 2 + w;
    const int cnt = g_cnt[q];

    const float* gd = g_bufd + (size_t)q * CAP;
    const int*   gi = g_bufi + (size_t)q * CAP;
    const float* pd; const int* pi;
    if (cnt <= SMAX) {
        for (int i = lane; i < cnt; i += 32) { sd[w][i] = gd[i]; si[w][i] = gi[i]; }
        __syncwarp();
        pd = sd[w]; pi = si[w];
    } else {
        pd = gd; pi = gi;
    }

    // exact 100th smallest (bits; all values clamped >= 0)
    unsigned lo = 0u, hi = 0x7f800000u;
    while (lo < hi) {
        unsigned mid = lo + ((hi - lo) >> 1);
        int c = 0;
        for (int i = lane; i < cnt; i += 32)
            c += (__float_as_uint(pd[i]) <= mid) ? 1 : 0;
        c = warp_sum_i(c);
        if (c >= KNN) hi = mid; else lo = mid + 1u;
    }
    const unsigned Tb = lo;

    int* out = g_topk + (size_t)q * KNN;
    const unsigned lt = (1u << lane) - 1u;
    int nout = 0, ntie = 0;
    for (int base = 0; base < cnt; base += 32) {
        int i = base + lane;
        bool v = (i < cnt);
        unsigned b = v ? __float_as_uint(pd[i]) : 0xffffffffu;
        bool w1 = (b < Tb);
        unsigned m1 = __ballot_sync(FULLM, w1);
        if (w1) out[nout + __popc(m1 & lt)] = pi[i];
        nout += __popc(m1);
        bool w2 = v && (b == Tb);
        unsigned m2 = __ballot_sync(FULLM, w2);
        if (w2) {
            int p = ntie + __popc(m2 & lt);
            if (p < 32) s_tie[w][p] = pi[i];
        }
        ntie += __popc(m2);
    }
    __syncwarp();

    const int tc = min(ntie, 32);
    const int need = KNN - nout;      // >= 1, <= 100
    for (int r = 0; r < need; r++) {
        int v = (lane < tc) ? s_tie[w][lane] : 0x7fffffff;
        int mv = warp_min_i(v);
        if (lane < tc && s_tie[w][lane] == mv) s_tie[w][lane] = 0x7fffffff;
        if (lane == 0) out[nout + r] = mv;
        __syncwarp();
    }
}

// ================= kernel 3: gather attention + residual(2x) + LN ==========
__global__ void __launch_bounds__(CDIM) attn_ln(
    const float* __restrict__ qf, const float* __restrict__ kf,
    const float* __restrict__ vf, const float* __restrict__ gamma,
    const float* __restrict__ beta, float* __restrict__ out)
{
    const int q = blockIdx.x;
    const int tid = threadIdx.x, lane = tid & 31, warp = tid >> 5;

    __shared__ int    s_idx[KNN];
    __shared__ float  s_logit[KNN];
    __shared__ float  s_p[KNN];
    __shared__ float4 s_part[3][64];
    __shared__ float4 s_x4[64];
    __shared__ float  s_red[8];
    __shared__ float  s_mean, s_rstd, s_inv;

    if (tid < KNN) s_idx[tid] = g_topk[(size_t)q * KNN + tid];

    const float4* qf4 = (const float4*)(qf + (size_t)q * CDIM);
    const float4  qa = qf4[lane], qb = qf4[32 + lane];
    __syncthreads();

    // QK^T logits: warp per neighbor, float4 loads
    for (int n = warp; n < KNN; n += 8) {
        const float4* kr = (const float4*)(kf + (size_t)s_idx[n] * CDIM);
        float4 ka = kr[lane], kb = kr[32 + lane];
        float s = qa.x * ka.x;
        s = fmaf(qa.y, ka.y, s); s = fmaf(qa.z, ka.z, s); s = fmaf(qa.w, ka.w, s);
        s = fmaf(qb.x, kb.x, s); s = fmaf(qb.y, kb.y, s);
        s = fmaf(qb.z, kb.z, s); s = fmaf(qb.w, kb.w, s);
        s = warp_sum_f(s);
        if (lane == 0) s_logit[n] = s * 0.0625f;   // C^-0.5 = 1/16
    }
    __syncthreads();

    // softmax (warp 0)
    if (warp == 0) {
        float mx = -CUDART_INF_F;
        for (int i = lane; i < KNN; i += 32) mx = fmaxf(mx, s_logit[i]);
        mx = warp_max_f(mx);
        float sm = 0.f;
        for (int i = lane; i < KNN; i += 32) {
            float e = __expf(s_logit[i] - mx);
            s_p[i] = e; sm += e;
        }
        sm = warp_sum_f(sm);
        if (lane == 0) s_inv = 1.f / sm;
    }
    __syncthreads();

    // PV: 4 neighbor-groups x 64 float4 channel slots
    const int g = warp >> 1;
    const int col = (warp & 1) * 32 + lane;   // 0..63
    float4 acc = make_float4(0.f, 0.f, 0.f, 0.f);
#pragma unroll 4
    for (int n = g; n < KNN; n += 4) {
        const float4* vr = (const float4*)(vf + (size_t)s_idx[n] * CDIM);
        float4 vv = vr[col];
        float p = s_p[n];
        acc.x = fmaf(p, vv.x, acc.x);
        acc.y = fmaf(p, vv.y, acc.y);
        acc.z = fmaf(p, vv.z, acc.z);
        acc.w = fmaf(p, vv.w, acc.w);
    }
    if (g) s_part[g - 1][col] = acc;
    __syncthreads();
    if (g == 0) {
        float4 a = s_part[0][col], b = s_part[1][col], c = s_part[2][col];
        float sc = 2.f * s_inv;                 // res fully overwritten: y = 2x
        s_x4[col] = make_float4((acc.x + a.x + b.x + c.x) * sc,
                                (acc.y + a.y + b.y + c.y) * sc,
                                (acc.z + a.z + b.z + c.z) * sc,
                                (acc.w + a.w + b.w + c.w) * sc);
    }
    __syncthreads();

    // LayerNorm over CDIM
    float y = ((const float*)s_x4)[tid];
    float s = warp_sum_f(y);
    if (lane == 0) s_red[warp] = s;
    __syncthreads();
    if (warp == 0) {
        float v = (lane < 8) ? s_red[lane] : 0.f;
        v = warp_sum_f(v);
        if (lane == 0) s_mean = v * (1.f / CDIM);
    }
    __syncthreads();
    float d = y - s_mean;
    float s2 = warp_sum_f(d * d);
    if (lane == 0) s_red[warp] = s2;
    __syncthreads();
    if (warp == 0) {
        float v = (lane < 8) ? s_red[lane] : 0.f;
        v = warp_sum_f(v);
        if (lane == 0) s_rstd = rsqrtf(v * (1.f / CDIM) + 1e-5f);
    }
    __syncthreads();

    out[(size_t)q * CDIM + tid] = d * s_rstd * gamma[tid] + beta[tid];
}

// ---------------- launch ----------------
extern "C" void kernel_launch(void* const* d_in, const int* in_sizes, int n_in,
                              void* d_out, int out_size) {
    (void)in_sizes; (void)n_in; (void)out_size;
    const float* qf    = (const float*)d_in[1];
    const float* kf    = (const float*)d_in[2];
    const float* vf    = (const float*)d_in[3];
    const float* qpos  = (const float*)d_in[4];
    const float* kpos  = (const float*)d_in[5];
    const float* gamma = (const float*)d_in[6];
    const float* beta  = (const float*)d_in[7];

    knn_scan<<<NQ / (WPB * QPW), 32 * WPB>>>(qpos, kpos);
    knn_final<<<NQ / 2, 64>>>();
    attn_ln<<<NQ, CDIM>>>(qf, kf, vf, gamma, beta, (float*)d_out);
}

// round 4
// speedup vs baseline: 1.5424x; 1.5424x over previous
#include <cuda_runtime.h>
#include <math_constants.h>

#define NQ     4096
#define NKV    32768
#define CDIM   256
#define KNN    100
#define NSPLIT 4
#define RANGE  (NKV / NSPLIT)     // 8192
#define TILE   2048
#define CAPS   1024               // per (query,split) segment capacity
#define SMAX   (NSPLIT * CAPS)    // 4096
#define QPW    4
#define WPB    4
#define FULLM  0xffffffffu

// ---------------- static scratch ----------------
__device__ uint2 g_buf[(size_t)NQ * NSPLIT * CAPS];  // {d2 bits (clamped>=0), kv idx}
__device__ int   g_cnt[NQ * NSPLIT];
__device__ int   g_topk[(size_t)NQ * KNN];

// ---------------- helpers ----------------
__device__ __forceinline__ int warp_sum_i(int v) {
#pragma unroll
    for (int o = 16; o; o >>= 1) v += __shfl_xor_sync(FULLM, v, o);
    return v;
}
__device__ __forceinline__ float warp_sum_f(float v) {
#pragma unroll
    for (int o = 16; o; o >>= 1) v += __shfl_xor_sync(FULLM, v, o);
    return v;
}
__device__ __forceinline__ float warp_max_f(float v) {
#pragma unroll
    for (int o = 16; o; o >>= 1) v = fmaxf(v, __shfl_xor_sync(FULLM, v, o));
    return v;
}
__device__ __forceinline__ int warp_min_i(int v) {
#pragma unroll
    for (int o = 16; o; o >>= 1) v = min(v, __shfl_xor_sync(FULLM, v, o));
    return v;
}

// ================= kernel 1: candidate scan (KV-split) =================
// grid = (NQ/16, NSPLIT). Each warp: 4 queries over one 8192-wide KV range.
// Sample (first 2048 of range) -> per-lane sorted-4 stash -> safe threshold
// (>= true global 100th). Scan appends admits to private (q,split) segment.
__global__ void __launch_bounds__(32 * WPB) knn_scan(
    const float* __restrict__ qpos, const float* __restrict__ kpos)
{
    __shared__ float4 s_tile[TILE];

    const int tid = threadIdx.x, lane = tid & 31, warp = tid >> 5;
    const int qbase = blockIdx.x * (WPB * QPW) + warp * QPW;
    const int split = blockIdx.y;
    const int kbase = split * RANGE;
    const unsigned lt = (1u << lane) - 1u;

    float ax[QPW], ay[QPW], az[QPW], c0[QPW], thr[QPW];
    int cnt[QPW];
#pragma unroll
    for (int j = 0; j < QPW; j++) {
        int q = qbase + j;
        float qx = qpos[3 * q], qy = qpos[3 * q + 1], qz = qpos[3 * q + 2];
        c0[j] = fmaf(qx, qx, fmaf(qy, qy, qz * qz));
        ax[j] = -2.f * qx; ay[j] = -2.f * qy; az[j] = -2.f * qz;
        cnt[j] = 0;
    }

    // ---- load tile A (first 2048 of range) ----
    for (int i = tid; i < TILE; i += 32 * WPB) {
        int g = kbase + i;
        float x = kpos[3 * g], y = kpos[3 * g + 1], z = kpos[3 * g + 2];
        s_tile[i] = make_float4(x, y, z, fmaf(x, x, fmaf(y, y, z * z)));
    }
    __syncthreads();

    // ---- sample phase over tile A: per-lane sorted-4 minima ----
    {
        float m[QPW][4];
#pragma unroll
        for (int j = 0; j < QPW; j++)
#pragma unroll
            for (int s = 0; s < 4; s++) m[j][s] = CUDART_INF_F;

        for (int i = lane; i < TILE; i += 32) {
            float4 kp = s_tile[i];
#pragma unroll
            for (int j = 0; j < QPW; j++) {
                float d = fmaf(ax[j], kp.x, c0[j] + kp.w);
                d = fmaf(ay[j], kp.y, d);
                d = fmaf(az[j], kp.z, d);
                d = fmaxf(d, 0.f);
                float t0 = fminf(m[j][0], d), t1 = fmaxf(m[j][0], d); m[j][0] = t0;
                float t2 = fminf(m[j][1], t1), t3 = fmaxf(m[j][1], t1); m[j][1] = t2;
                float t4 = fminf(m[j][2], t3), t5 = fmaxf(m[j][2], t3); m[j][2] = t4;
                m[j][3] = fminf(m[j][3], t5);
            }
        }
        // threshold = kth (k=100) of the 128 stash values: upper bound on the
        // sample 100th, which upper-bounds the global 100th -> safe filter.
#pragma unroll
        for (int j = 0; j < QPW; j++) {
            unsigned lo = 0u, hi = 0x7f800000u;
#pragma unroll
            for (int it = 0; it < 16; it++) {
                unsigned mid = lo + ((hi - lo) >> 1);
                int c = 0;
#pragma unroll
                for (int s = 0; s < 4; s++) c += (__float_as_uint(m[j][s]) <= mid) ? 1 : 0;
                c = warp_sum_i(c);
                if (c >= KNN) hi = mid; else lo = mid + 1u;
            }
            thr[j] = __uint_as_float(hi);
        }
    }

    // ---- main scan: tile A (resident), then remaining tiles ----
    uint2* seg[QPW];
#pragma unroll
    for (int j = 0; j < QPW; j++)
        seg[j] = g_buf + ((size_t)(qbase + j) * NSPLIT + split) * CAPS;

    for (int t0 = 0; t0 < RANGE; t0 += TILE) {
        if (t0) {
            __syncthreads();
            for (int i = tid; i < TILE; i += 32 * WPB) {
                int g = kbase + t0 + i;
                float x = kpos[3 * g], y = kpos[3 * g + 1], z = kpos[3 * g + 2];
                s_tile[i] = make_float4(x, y, z, fmaf(x, x, fmaf(y, y, z * z)));
            }
            __syncthreads();
        }
        for (int i = lane; i < TILE; i += 32) {
            float4 kp = s_tile[i];
#pragma unroll
            for (int j = 0; j < QPW; j++) {
                float d = fmaf(ax[j], kp.x, c0[j] + kp.w);
                d = fmaf(ay[j], kp.y, d);
                d = fmaf(az[j], kp.z, d);
                bool p = (d <= thr[j]);
                unsigned m = __ballot_sync(FULLM, p);
                int pos = cnt[j] + __popc(m & lt);
                if (p && pos < CAPS)
                    seg[j][pos] = make_uint2(__float_as_uint(fmaxf(d, 0.f)),
                                             (unsigned)(kbase + t0 + i));
                cnt[j] += __popc(m);
            }
        }
    }
    if (lane == 0) {
#pragma unroll
        for (int j = 0; j < QPW; j++)
            g_cnt[(qbase + j) * NSPLIT + split] = min(cnt[j], CAPS);
    }
}

// ================= kernel 2: exact top-100 merge =================
// One warp per query (block=32). Merge 4 segments into smem, exact 100th
// value by binary search on bits, ties -> smallest kv indices.
__global__ void __launch_bounds__(32) knn_final()
{
    __shared__ uint2 s_c[SMAX];
    __shared__ int   s_tie[32];

    const int lane = threadIdx.x;
    const int q = blockIdx.x;
    const unsigned lt = (1u << lane) - 1u;

    int tot = 0;
#pragma unroll
    for (int s = 0; s < NSPLIT; s++) {
        const int c = g_cnt[q * NSPLIT + s];
        const uint2* src = g_buf + ((size_t)q * NSPLIT + s) * CAPS;
        for (int i = lane; i < c; i += 32) s_c[tot + i] = src[i];
        tot += c;
    }
    __syncwarp();

    // exact 100th smallest (bit order == value order; values clamped >= 0)
    unsigned lo = 0u, hi = 0x7f800000u;
    while (lo < hi) {
        unsigned mid = lo + ((hi - lo) >> 1);
        int c = 0;
        for (int i = lane; i < tot; i += 32) c += (s_c[i].x <= mid) ? 1 : 0;
        c = warp_sum_i(c);
        if (c >= KNN) hi = mid; else lo = mid + 1u;
    }
    const unsigned Tb = lo;

    int* out = g_topk + (size_t)q * KNN;
    int nout = 0, ntie = 0;
    for (int base = 0; base < tot; base += 32) {
        int i = base + lane;
        bool v = (i < tot);
        unsigned b = v ? s_c[i].x : 0xffffffffu;
        bool w1 = (b < Tb);
        unsigned m1 = __ballot_sync(FULLM, w1);
        if (w1) out[nout + __popc(m1 & lt)] = (int)s_c[i].y;
        nout += __popc(m1);
        bool w2 = v && (b == Tb);
        unsigned m2 = __ballot_sync(FULLM, w2);
        if (w2) {
            int p = ntie + __popc(m2 & lt);
            if (p < 32) s_tie[p] = (int)s_c[i].y;
        }
        ntie += __popc(m2);
    }
    __syncwarp();

    const int tc = min(ntie, 32);
    const int need = KNN - nout;
    for (int r = 0; r < need; r++) {
        int v = (lane < tc) ? s_tie[lane] : 0x7fffffff;
        int mv = warp_min_i(v);
        if (lane < tc && s_tie[lane] == mv) s_tie[lane] = 0x7fffffff;
        if (lane == 0) out[nout + r] = mv;
        __syncwarp();
    }
}

// ================= kernel 3: gather attention + residual(2x) + LN ==========
__global__ void __launch_bounds__(CDIM) attn_ln(
    const float* __restrict__ qf, const float* __restrict__ kf,
    const float* __restrict__ vf, const float* __restrict__ gamma,
    const float* __restrict__ beta, float* __restrict__ out)
{
    const int q = blockIdx.x;
    const int tid = threadIdx.x, lane = tid & 31, warp = tid >> 5;

    __shared__ int    s_idx[KNN];
    __shared__ float  s_logit[KNN];
    __shared__ float  s_p[KNN];
    __shared__ float4 s_part[3][64];
    __shared__ float4 s_x4[64];
    __shared__ float  s_red[8];
    __shared__ float  s_mean, s_rstd, s_inv;

    if (tid < KNN) s_idx[tid] = g_topk[(size_t)q * KNN + tid];

    const float4* qf4 = (const float4*)(qf + (size_t)q * CDIM);
    const float4  qa = qf4[lane], qb = qf4[32 + lane];
    __syncthreads();

    // QK^T: two neighbors per reduction round (interleaved shuffle chains)
    for (int n = warp; n < KNN; n += 16) {
        const int n2 = n + 8;
        const bool has2 = (n2 < KNN);
        const float4* kr1 = (const float4*)(kf + (size_t)s_idx[n] * CDIM);
        const float4* kr2 = (const float4*)(kf + (size_t)s_idx[has2 ? n2 : n] * CDIM);
        float4 ka1 = kr1[lane], kb1 = kr1[32 + lane];
        float4 ka2 = kr2[lane], kb2 = kr2[32 + lane];
        float s1 = qa.x * ka1.x, s2 = qa.x * ka2.x;
        s1 = fmaf(qa.y, ka1.y, s1);  s2 = fmaf(qa.y, ka2.y, s2);
        s1 = fmaf(qa.z, ka1.z, s1);  s2 = fmaf(qa.z, ka2.z, s2);
        s1 = fmaf(qa.w, ka1.w, s1);  s2 = fmaf(qa.w, ka2.w, s2);
        s1 = fmaf(qb.x, kb1.x, s1);  s2 = fmaf(qb.x, kb2.x, s2);
        s1 = fmaf(qb.y, kb1.y, s1);  s2 = fmaf(qb.y, kb2.y, s2);
        s1 = fmaf(qb.z, kb1.z, s1);  s2 = fmaf(qb.z, kb2.z, s2);
        s1 = fmaf(qb.w, kb1.w, s1);  s2 = fmaf(qb.w, kb2.w, s2);
#pragma unroll
        for (int o = 16; o; o >>= 1) {
            s1 += __shfl_xor_sync(FULLM, s1, o);
            s2 += __shfl_xor_sync(FULLM, s2, o);
        }
        if (lane == 0) {
            s_logit[n] = s1 * 0.0625f;                 // C^-0.5 = 1/16
            if (has2) s_logit[n2] = s2 * 0.0625f;
        }
    }
    __syncthreads();

    // softmax (warp 0)
    if (warp == 0) {
        float mx = -CUDART_INF_F;
        for (int i = lane; i < KNN; i += 32) mx = fmaxf(mx, s_logit[i]);
        mx = warp_max_f(mx);
        float sm = 0.f;
        for (int i = lane; i < KNN; i += 32) {
            float e = __expf(s_logit[i] - mx);
            s_p[i] = e; sm += e;
        }
        sm = warp_sum_f(sm);
        if (lane == 0) s_inv = 1.f / sm;
    }
    __syncthreads();

    // PV: 4 neighbor-groups x 64 float4 channel slots
    const int g = warp >> 1;
    const int col = (warp & 1) * 32 + lane;
    float4 acc = make_float4(0.f, 0.f, 0.f, 0.f);
#pragma unroll 4
    for (int n = g; n < KNN; n += 4) {
        const float4* vr = (const float4*)(vf + (size_t)s_idx[n] * CDIM);
        float4 vv = vr[col];
        float p = s_p[n];
        acc.x = fmaf(p, vv.x, acc.x);
        acc.y = fmaf(p, vv.y, acc.y);
        acc.z = fmaf(p, vv.z, acc.z);
        acc.w = fmaf(p, vv.w, acc.w);
    }
    if (g) s_part[g - 1][col] = acc;
    __syncthreads();
    if (g == 0) {
        float4 a = s_part[0][col], b = s_part[1][col], c = s_part[2][col];
        float sc = 2.f * s_inv;                        // res fully overwritten: y = 2x
        s_x4[col] = make_float4((acc.x + a.x + b.x + c.x) * sc,
                                (acc.y + a.y + b.y + c.y) * sc,
                                (acc.z + a.z + b.z + c.z) * sc,
                                (acc.w + a.w + b.w + c.w) * sc);
    }
    __syncthreads();

    // LayerNorm over CDIM
    float y = ((const float*)s_x4)[tid];
    float s = warp_sum_f(y);
    if (lane == 0) s_red[warp] = s;
    __syncthreads();
    if (warp == 0) {
        float v = (lane < 8) ? s_red[lane] : 0.f;
        v = warp_sum_f(v);
        if (lane == 0) s_mean = v * (1.f / CDIM);
    }
    __syncthreads();
    float d = y - s_mean;
    float s2 = warp_sum_f(d * d);
    if (lane == 0) s_red[warp] = s2;
    __syncthreads();
    if (warp == 0) {
        float v = (lane < 8) ? s_red[lane] : 0.f;
        v = warp_sum_f(v);
        if (lane == 0) s_rstd = rsqrtf(v * (1.f / CDIM) + 1e-5f);
    }
    __syncthreads();

    out[(size_t)q * CDIM + tid] = d * s_rstd * gamma[tid] + beta[tid];
}

// ---------------- launch ----------------
extern "C" void kernel_launch(void* const* d_in, const int* in_sizes, int n_in,
                              void* d_out, int out_size) {
    (void)in_sizes; (void)n_in; (void)out_size;
    const float* qf    = (const float*)d_in[1];
    const float* kf    = (const float*)d_in[2];
    const float* vf    = (const float*)d_in[3];
    const float* qpos  = (const float*)d_in[4];
    const float* kpos  = (const float*)d_in[5];
    const float* gamma = (const float*)d_in[6];
    const float* beta  = (const float*)d_in[7];

    knn_scan<<<dim3(NQ / (WPB * QPW), NSPLIT), 32 * WPB>>>(qpos, kpos);
    knn_final<<<NQ, 32>>>();
    attn_ln<<<NQ, CDIM>>>(qf, kf, vf, gamma, beta, (float*)d_out);
}